// round 8
// baseline (speedup 1.0000x reference)
#include <cuda_runtime.h>

// EKVNonLinearConv, branch-free w-space table.
//   f(d) = sp(min(a,20))^2 - sp(min(a-D,20))^2, a=d/0.075, D=0.1/0.075
//   w = clamp(1 + (d + 0.96)/2.56, [1.0, 2.0-ulp]); idx = top 9 mantissa bits of w.
//   Table: f ~= a1*w + a0 on each of 512 intervals (h_d = 0.005; kinks d=1.5 -> 492,
//   d=1.6 -> right edge of 511, line hits 0 exactly there; d<<0 -> entry 0 ~ 5e-12).
//   Inactive lanes all broadcast-load tab[0] -> negligible crossbar cost.
//   out = ALPHA*R*scale * sum_l f(vg - th)

#define CIN    16
#define COUTT  64
#define HH     32
#define WW     32
#define BB     8
#define CG     4      // couts per block
#define RPB    8      // output rows per block
#define NTHR   256    // 8 warps, one output row per warp
#define LPC    144    // CIN*3*3

#define TABN   512
#define TD0    (-0.96f)
#define THD    0.005f               // 2.56/512
#define WSCALE 0.390625f            // 1/2.56 (exact dyadic)
#define WMAX   1.9999998807907104f  // largest float < 2.0

__device__ __forceinline__ float ekv_exact(float d) {
    const float INVD  = 13.333333333333334f;
    const float DELTA = 1.3333333333333333f;
    float a  = d * INVD;
    float a1 = fminf(fmaxf(a, -50.0f), 20.0f);
    float a2 = fminf(fmaxf(a - DELTA, -50.0f), 20.0f);
    float l1 = log1pf(expf(a1));
    float l2 = log1pf(expf(a2));
    return fmaf(l1, l1, -l2 * l2);
}

__global__ __launch_bounds__(NTHR)
void ekv_conv_kernel(const float* __restrict__ x,
                     const float* __restrict__ theta,
                     const float* __restrict__ scale,
                     float* __restrict__ out)
{
    __shared__ float  sx[CIN][RPB + 2][34];   // halo tile (21.76 KB)
    __shared__ float4 swb[CG][CIN * 3];       // wb per (c, ci*3+ky), kx triple (3 KB)
    __shared__ float2 tab[TABN];              // 4 KB, w-space lines

    const int rt = blockIdx.x;       // row tile 0..3
    const int cg = blockIdx.y;       // cout group 0..15
    const int b  = blockIdx.z;       // batch
    const int y0 = rt * RPB;
    const int c0 = cg * CG;
    const int tid = threadIdx.x;

    // ---- build table in-kernel (2 entries per thread) ----
    for (int i = tid; i < TABN; i += NTHR) {
        float d0 = TD0 + (float)i * THD;
        float f0 = ekv_exact(d0);
        float f1 = ekv_exact(d0 + THD);
        float a1 = (f1 - f0) * 512.0f;                 // slope per unit w
        float w0 = 1.0f + (float)i * (1.0f / 512.0f);
        tab[i] = make_float2(fmaf(-a1, w0, f0), a1);
    }

    // ---- load x halo tile (zero-padded) ----
    for (int i = tid; i < CIN * (RPB + 2) * 34; i += NTHR) {
        int cc = i % 34;
        int r  = (i / 34) % (RPB + 2);
        int ci = i / (34 * (RPB + 2));
        int gy = y0 - 1 + r;
        int gx = cc - 1;
        float v = 0.0f;
        if (gy >= 0 && gy < HH && gx >= 0 && gx < WW)
            v = x[((b * CIN + ci) * HH + gy) * WW + gx];
        sx[ci][r][cc] = v;
    }
    // ---- theta -> wb = 1 + (0.96 - clip(th)) / 2.56, packed per kx-triple ----
    for (int i = tid; i < CG * CIN * 3; i += NTHR) {
        int g = i % (CIN * 3);           // ci*3 + ky
        int c = i / (CIN * 3);
        const float* tp = theta + (c0 + c) * LPC + g * 3;
        float t0 = fminf(fmaxf(tp[0], 1.0f), 8.0f);
        float t1 = fminf(fmaxf(tp[1], 1.0f), 8.0f);
        float t2 = fminf(fmaxf(tp[2], 1.0f), 8.0f);
        swb[c][g] = make_float4(fmaf(0.96f - t0, WSCALE, 1.0f),
                                fmaf(0.96f - t1, WSCALE, 1.0f),
                                fmaf(0.96f - t2, WSCALE, 1.0f), 0.0f);
    }
    __syncthreads();

    const int tx = tid & 31;    // output column
    const int ty = tid >> 5;    // output row within tile (warp id 0..7)

    float acc0 = 0.0f, acc1 = 0.0f, acc2 = 0.0f, acc3 = 0.0f;
    const char* tabb = (const char*)tab;

#define EKV_TERM(VG, WB, ACC) do {                                   \
        float w_ = fmaf((VG), WSCALE, (WB));                         \
        w_ = fmaxf(w_, 1.0f);                                        \
        w_ = fminf(w_, WMAX);                                        \
        int off_ = (__float_as_int(w_) >> 11) & 0xFF8;               \
        float2 e_ = *(const float2*)(tabb + off_);                   \
        float f_ = fmaf(e_.y, w_, e_.x);                             \
        (ACC) += f_;                                                 \
    } while (0)

    #pragma unroll 2
    for (int ci = 0; ci < CIN; ci++) {
        #pragma unroll
        for (int ky = 0; ky < 3; ky++) {
            const float vg0 = sx[ci][ty + ky][tx + 0];
            const float vg1 = sx[ci][ty + ky][tx + 1];
            const float vg2 = sx[ci][ty + ky][tx + 2];
            const int g = ci * 3 + ky;
            {
                float4 wb = swb[0][g];
                EKV_TERM(vg0, wb.x, acc0);
                EKV_TERM(vg1, wb.y, acc0);
                EKV_TERM(vg2, wb.z, acc0);
            }
            {
                float4 wb = swb[1][g];
                EKV_TERM(vg0, wb.x, acc1);
                EKV_TERM(vg1, wb.y, acc1);
                EKV_TERM(vg2, wb.z, acc1);
            }
            {
                float4 wb = swb[2][g];
                EKV_TERM(vg0, wb.x, acc2);
                EKV_TERM(vg1, wb.y, acc2);
                EKV_TERM(vg2, wb.z, acc2);
            }
            {
                float4 wb = swb[3][g];
                EKV_TERM(vg0, wb.x, acc3);
                EKV_TERM(vg1, wb.y, acc3);
                EKV_TERM(vg2, wb.z, acc3);
            }
        }
    }
#undef EKV_TERM

    const float sc = scale[0] * (0.05625f * 0.1f);   // ALPHA * R * scale
    const int y = y0 + ty;
    out[((b * COUTT + (c0 + 0)) * HH + y) * WW + tx] = acc0 * sc;
    out[((b * COUTT + (c0 + 1)) * HH + y) * WW + tx] = acc1 * sc;
    out[((b * COUTT + (c0 + 2)) * HH + y) * WW + tx] = acc2 * sc;
    out[((b * COUTT + (c0 + 3)) * HH + y) * WW + tx] = acc3 * sc;
}

extern "C" void kernel_launch(void* const* d_in, const int* in_sizes, int n_in,
                              void* d_out, int out_size) {
    const float* x     = (const float*)d_in[0];
    const float* theta = (const float*)d_in[1];
    const float* scale = (const float*)d_in[2];
    float* out = (float*)d_out;
    (void)in_sizes; (void)n_in; (void)out_size;

    dim3 grid(HH / RPB, COUTT / CG, BB);   // 4 x 16 x 8 = 512 blocks
    dim3 block(NTHR);
    ekv_conv_kernel<<<grid, block>>>(x, theta, scale, out);
}

// round 9
// speedup vs baseline: 1.2551x; 1.2551x over previous
#include <cuda_runtime.h>

// EKVNonLinearConv, u-space table + warp-uniform skip, 2 output rows per thread.
//   f(d) = sp(min(a,20))^2 - sp(min(a-D,20))^2, a=d/0.075, D=0.1/0.075
//   u = saturate(vg*INVR + ub), ub = (0.96 - clip(th,1,8))/2.58 + 0 (folded)
//   idx = floor(u*516); tab entries >= 512 are exact zero (d >= 1.6).
//   Kinks d=1.5 -> 492, d=1.6 -> 512 (on-grid). u==1 -> idx 516 (zero entry).
//   out = ALPHA*R*scale * sum_l f(vg - th)

#define CIN    16
#define COUTT  64
#define HH     32
#define WW     32
#define BB     8
#define CG     2      // couts per block
#define PR     2      // output rows per thread
#define NWARP  8
#define NTHR   256
#define RPB    (NWARP * PR)   // 16 output rows per block
#define TILR   (RPB + 2)      // 18 tile rows incl halo
#define LPC    144

#define TABN   516
#define TABEXT 518
#define TD0    (-0.96f)
#define THD    0.005f
#define INVR   0.3875968992248062f   // 1/2.58
#define USCALE 516.0f

__device__ float2 g_tab[TABEXT]; // (a0, a1): f ~= a1*u + a0 on interval i

__device__ __forceinline__ float ekv_exact(float d) {
    const float INVD  = 13.333333333333334f;
    const float DELTA = 1.3333333333333333f;
    float a  = d * INVD;
    float a1 = fminf(fmaxf(a, -50.0f), 20.0f);
    float a2 = fminf(fmaxf(a - DELTA, -50.0f), 20.0f);
    float l1 = log1pf(expf(a1));
    float l2 = log1pf(expf(a2));
    return fmaf(l1, l1, -l2 * l2);
}

__global__ void build_table_kernel() {
    int i = blockIdx.x * blockDim.x + threadIdx.x;
    if (i < TABEXT) {
        float f0 = ekv_exact(TD0 + (float)i * THD);
        float f1 = ekv_exact(TD0 + (float)(i + 1) * THD);
        float a1 = (f1 - f0) * USCALE;           // slope per unit u
        float u0 = (float)i * (1.0f / USCALE);
        g_tab[i] = make_float2(fmaf(-a1, u0, f0), a1);   // i>=512: exact (0,0)
    }
}

__global__ __launch_bounds__(NTHR)
void ekv_conv_kernel(const float* __restrict__ x,
                     const float* __restrict__ theta,
                     const float* __restrict__ scale,
                     float* __restrict__ out)
{
    __shared__ float  sx[CIN][TILR][34];     // halo tile (38.25 KB)
    __shared__ float4 swb[CG][CIN * 3];      // ub per (c, ci*3+ky), kx triple
    __shared__ float  sthr[CIN][TILR];       // (0.11 - rowmax)*INVR
    __shared__ float2 tab[TABEXT];           // ~4 KB

    const int rt = blockIdx.x;       // row tile 0..1
    const int cg = blockIdx.y;       // cout group 0..31
    const int b  = blockIdx.z;       // batch
    const int y0 = rt * RPB;
    const int c0 = cg * CG;
    const int tid = threadIdx.x;

    // ---- copy table from global (L2-hot) ----
    {
        const float4* src = (const float4*)g_tab;
        float4*       dst = (float4*)tab;
        for (int i = tid; i < TABEXT / 2; i += NTHR) dst[i] = src[i];
    }

    // ---- load x halo tile (zero-padded) ----
    for (int i = tid; i < CIN * TILR * 34; i += NTHR) {
        int cc = i % 34;
        int r  = (i / 34) % TILR;
        int ci = i / (34 * TILR);
        int gy = y0 - 1 + r;
        int gx = cc - 1;
        float v = 0.0f;
        if (gy >= 0 && gy < HH && gx >= 0 && gx < WW)
            v = x[((b * CIN + ci) * HH + gy) * WW + gx];
        sx[ci][r][cc] = v;
    }
    // ---- theta -> ub = (0.96 - clip(th)) / 2.58, packed per kx-triple ----
    for (int i = tid; i < CG * CIN * 3; i += NTHR) {
        int g = i % (CIN * 3);           // ci*3 + ky
        int c = i / (CIN * 3);
        const float* tp = theta + (c0 + c) * LPC + g * 3;
        float t0 = fminf(fmaxf(tp[0], 1.0f), 8.0f);
        float t1 = fminf(fmaxf(tp[1], 1.0f), 8.0f);
        float t2 = fminf(fmaxf(tp[2], 1.0f), 8.0f);
        swb[c][g] = make_float4((0.96f - t0) * INVR,
                                (0.96f - t1) * INVR,
                                (0.96f - t2) * INVR, 0.0f);
    }
    __syncthreads();

    // ---- per-(ci,row) skip threshold: term active iff ub > sthr ----
    for (int i = tid; i < CIN * TILR; i += NTHR) {
        int r  = i % TILR;
        int ci = i / TILR;
        float m = -1e30f;
        #pragma unroll
        for (int cc = 0; cc < 34; cc++) m = fmaxf(m, sx[ci][r][cc]);
        sthr[ci][r] = (0.11f - m) * INVR;
    }
    __syncthreads();

    const int tx  = tid & 31;    // output column
    const int wid = tid >> 5;    // warp id 0..7; warp handles rows y0+2*wid, +1

    float accA0 = 0.0f, accB0 = 0.0f;   // cout c0,   rows A/B
    float accA1 = 0.0f, accB1 = 0.0f;   // cout c0+1, rows A/B

#define EKV_TERM(VG, UB, ACC) do {                                   \
        float u_ = __saturatef(fmaf((VG), INVR, (UB)));              \
        int idx_ = __float2int_rd(u_ * USCALE);                      \
        float2 e_ = tab[idx_];                                       \
        (ACC) += fmaf(e_.y, u_, e_.x);                               \
    } while (0)

    #pragma unroll 1
    for (int ci = 0; ci < CIN; ci++) {
        #pragma unroll
        for (int ky = 0; ky < 3; ky++) {
            const int r = wid * PR + ky;   // tile row for pixel-row A at this ky
            const float uthr = fminf(sthr[ci][r], sthr[ci][r + 1]);  // pair bound
            const float a0 = sx[ci][r][tx + 0];
            const float a1 = sx[ci][r][tx + 1];
            const float a2 = sx[ci][r][tx + 2];
            const float b0 = sx[ci][r + 1][tx + 0];
            const float b1 = sx[ci][r + 1][tx + 1];
            const float b2 = sx[ci][r + 1][tx + 2];
            const int g = ci * 3 + ky;
            {
                float4 ub = swb[0][g];
                if (ub.x > uthr) { EKV_TERM(a0, ub.x, accA0); EKV_TERM(b0, ub.x, accB0); }
                if (ub.y > uthr) { EKV_TERM(a1, ub.y, accA0); EKV_TERM(b1, ub.y, accB0); }
                if (ub.z > uthr) { EKV_TERM(a2, ub.z, accA0); EKV_TERM(b2, ub.z, accB0); }
            }
            {
                float4 ub = swb[1][g];
                if (ub.x > uthr) { EKV_TERM(a0, ub.x, accA1); EKV_TERM(b0, ub.x, accB1); }
                if (ub.y > uthr) { EKV_TERM(a1, ub.y, accA1); EKV_TERM(b1, ub.y, accB1); }
                if (ub.z > uthr) { EKV_TERM(a2, ub.z, accA1); EKV_TERM(b2, ub.z, accB1); }
            }
        }
    }
#undef EKV_TERM

    const float sc = scale[0] * (0.05625f * 0.1f);   // ALPHA * R * scale
    const int yA = y0 + wid * PR;
    const int yB = yA + 1;
    out[((b * COUTT + (c0 + 0)) * HH + yA) * WW + tx] = accA0 * sc;
    out[((b * COUTT + (c0 + 0)) * HH + yB) * WW + tx] = accB0 * sc;
    out[((b * COUTT + (c0 + 1)) * HH + yA) * WW + tx] = accA1 * sc;
    out[((b * COUTT + (c0 + 1)) * HH + yB) * WW + tx] = accB1 * sc;
}

extern "C" void kernel_launch(void* const* d_in, const int* in_sizes, int n_in,
                              void* d_out, int out_size) {
    const float* x     = (const float*)d_in[0];
    const float* theta = (const float*)d_in[1];
    const float* scale = (const float*)d_in[2];
    float* out = (float*)d_out;
    (void)in_sizes; (void)n_in; (void)out_size;

    build_table_kernel<<<3, 256>>>();

    dim3 grid(HH / RPB, COUTT / CG, BB);   // 2 x 32 x 8 = 512 blocks
    dim3 block(NTHR);
    ekv_conv_kernel<<<grid, block>>>(x, theta, scale, out);
}